// round 8
// baseline (speedup 1.0000x reference)
#include <cuda_runtime.h>
#include <cuda_bf16.h>

// Quadtree contraction: out[b][i] applies, at level k=1..10 (finest first),
//   choice c_k = bit_{k-1}(i):  c=0 -> x[2r,2c]+x[2r,2c+1]+x[2r+1,2c]
//                               c=1 -> x[2r+1,2c+1]
// Single fused kernel. Block = one 128x128 tile of one batch image:
//   levels 1..3 in registers, 4..7 in shared -> 128 scalars to g_scratch.
// The LAST block of each batch (fence+atomic counter) runs levels 8..10 for
// all 128 prefixes via warp shuffles, reading the just-written (L2-hot)
// scratch, and writes the batch's 1024 outputs. No second kernel launch.

static __device__ float g_scratch[64 * 128 * 64]; // 2 MB: [((b<<7)|p7)<<6 | tile]
static __device__ int   g_count[64];              // zero-init; reset each launch

__global__ __launch_bounds__(256) void cnndst_fused(const float* __restrict__ M,
                                                    float* __restrict__ out) {
    __shared__ float bufA[2048]; // level3 [p3(8)][t(256)], later level5 (512)
    __shared__ float bufB[1024]; // level4 [p4(16)][cell(64)], later level6 (256)
    __shared__ int   s_last;

    const int tid  = threadIdx.x;
    const int b    = blockIdx.y;
    const int tile = blockIdx.x;       // 0..63
    const int tr   = tile >> 3;
    const int tc   = tile & 7;

    // Thread's 8x8 fine block at rows (tid>>4)*8, cols (tid&15)*8 of the tile.
    const float* src = M + ((size_t)b << 20)
                         + ((size_t)((tr << 7) + ((tid >> 4) << 3))) * 1024
                         + (size_t)((tc << 7) + ((tid & 15) << 3));

    // Front-batched streaming loads (read-once input; evict-first keeps the
    // 256 MB stream from evicting g_scratch lines needed by the epilogue).
    float4 L[16];
    #pragma unroll
    for (int rr = 0; rr < 8; rr++) {
        L[2 * rr]     = __ldcs((const float4*)(src + (size_t)rr * 1024));
        L[2 * rr + 1] = __ldcs((const float4*)(src + (size_t)rr * 1024 + 4));
    }

    // Level 1 in registers: 4x4 S grid + 4x4 D grid.
    float s1[4][4], d1[4][4];
    #pragma unroll
    for (int rr = 0; rr < 4; rr++) {
        const float4 a0 = L[4 * rr],     a1 = L[4 * rr + 1];
        const float4 b0 = L[4 * rr + 2], b1 = L[4 * rr + 3];
        s1[rr][0] = (a0.x + a0.y) + b0.x;  d1[rr][0] = b0.y;
        s1[rr][1] = (a0.z + a0.w) + b0.z;  d1[rr][1] = b0.w;
        s1[rr][2] = (a1.x + a1.y) + b1.x;  d1[rr][2] = b1.y;
        s1[rr][3] = (a1.z + a1.w) + b1.z;  d1[rr][3] = b1.w;
    }
    // Level 2: p2 = c1 + 2*c2 -> grids 0:S(s1) 1:S(d1) 2:D(s1) 3:D(d1).
    float g2[4][2][2];
    #pragma unroll
    for (int r = 0; r < 2; r++)
        #pragma unroll
        for (int c = 0; c < 2; c++) {
            g2[0][r][c] = (s1[2*r][2*c] + s1[2*r][2*c+1]) + s1[2*r+1][2*c];
            g2[2][r][c] = s1[2*r+1][2*c+1];
            g2[1][r][c] = (d1[2*r][2*c] + d1[2*r][2*c+1]) + d1[2*r+1][2*c];
            g2[3][r][c] = d1[2*r+1][2*c+1];
        }
    // Level 3: thread sits at (tid>>4, tid&15) of each 16x16 level-3 grid.
    #pragma unroll
    for (int p = 0; p < 4; p++) {
        bufA[(p << 8) + tid]       = (g2[p][0][0] + g2[p][0][1]) + g2[p][1][0];
        bufA[((p + 4) << 8) + tid] = g2[p][1][1];
    }
    __syncthreads();

    // Level 4: 8 grids 16x16 -> 16 grids 8x8. 512 units, 2/thread.
    #pragma unroll
    for (int k = 0; k < 2; k++) {
        const int idx  = tid + (k << 8);
        const int p    = idx >> 6, cell = idx & 63;
        const int r    = cell >> 3, c = cell & 7;
        const float* in = bufA + (p << 8) + (r << 5) + (c << 1);
        bufB[(p << 6) + cell]       = (in[0] + in[1]) + in[16];
        bufB[((p + 8) << 6) + cell] = in[17];
    }
    __syncthreads();

    // Level 5: 16 grids 8x8 -> 32 grids 4x4. 256 units, 1/thread.
    {
        const int p = tid >> 4, cell = tid & 15;
        const int r = cell >> 2, c = cell & 3;
        const float* in = bufB + (p << 6) + (r << 4) + (c << 1);
        bufA[(p << 4) + cell]        = (in[0] + in[1]) + in[8];
        bufA[((p + 16) << 4) + cell] = in[9];
    }
    __syncthreads();

    // Level 6: 32 grids 4x4 -> 64 grids 2x2. 128 units.
    if (tid < 128) {
        const int p = tid >> 2, cell = tid & 3;
        const int r = cell >> 1, c = cell & 1;
        const float* in = bufA + (p << 4) + (r << 3) + (c << 1);
        bufB[(p << 2) + cell]        = (in[0] + in[1]) + in[4];
        bufB[((p + 32) << 2) + cell] = in[5];
    }
    __syncthreads();

    // Level 7: 64 grids 2x2 -> 128 scalars -> g_scratch.
    if (tid < 64) {
        const float* in = bufB + (tid << 2);
        const int base = (b << 7);
        g_scratch[((size_t)(base + tid) << 6) + tile]      = (in[0] + in[1]) + in[2];
        g_scratch[((size_t)(base + tid + 64) << 6) + tile] = in[3];
    }
    __syncthreads();   // all scratch writes of this block issued

    // Release writes, count this block. Last block of batch b runs epilogue.
    if (tid == 0) {
        __threadfence();
        const int old = atomicAdd(&g_count[b], 1);
        s_last = (old == 63);
        if (old == 63) g_count[b] = 0;   // replay-safe reset (all 64 arrived)
    }
    __syncthreads();
    if (!s_last) return;

    __threadfence();   // acquire: peers' scratch writes visible

    // Epilogue: levels 8..10 for all 128 prefixes of batch b.
    // Warp w handles p7 = w*16 .. w*16+15. Lane layout on the 8x8 grid:
    // k = reg*32 + lane, (r,c) = (k>>3, k&7).
    const int wid  = tid >> 5;
    const int lane = tid & 31;
    const unsigned FULL = 0xffffffffu;

    #pragma unroll 4
    for (int it = 0; it < 16; it++) {
        const int p7 = (wid << 4) + it;
        const float* g = g_scratch + (((size_t)((b << 7) + p7)) << 6);
        const float v0 = g[lane];
        const float v1 = g[32 + lane];

        // Level 8: 8x8 -> 2 grids 4x4 (valid at even r, even c lanes).
        float a1[2][2];
        {
            const float x01a = __shfl_xor_sync(FULL, v0, 1);
            const float x10a = __shfl_xor_sync(FULL, v0, 8);
            const float x11a = __shfl_xor_sync(FULL, v0, 9);
            a1[0][0] = (v0 + x01a) + x10a;
            a1[1][0] = x11a;
            const float x01b = __shfl_xor_sync(FULL, v1, 1);
            const float x10b = __shfl_xor_sync(FULL, v1, 8);
            const float x11b = __shfl_xor_sync(FULL, v1, 9);
            a1[0][1] = (v1 + x01b) + x10b;
            a1[1][1] = x11b;
        }
        // Level 9: sparse spacing 2 -> xor 2 horiz, 16 vert.
        float a2[4][2];
        #pragma unroll
        for (int p = 0; p < 2; p++)
            #pragma unroll
            for (int i = 0; i < 2; i++) {
                const float x00 = a1[p][i];
                const float x01 = __shfl_xor_sync(FULL, x00, 2);
                const float x10 = __shfl_xor_sync(FULL, x00, 16);
                const float x11 = __shfl_xor_sync(FULL, x00, 18);
                a2[p][i]     = (x00 + x01) + x10;
                a2[p + 2][i] = x11;
            }
        // Level 10: sparse spacing 4 -> xor 4 horiz; vertical = cross-reg.
        float a4[8];
        #pragma unroll
        for (int p = 0; p < 4; p++) {
            const float i0 = a2[p][0];
            const float i1 = a2[p][1];
            a4[p]     = (i0 + __shfl_xor_sync(FULL, i0, 4)) + i1;
            a4[p + 4] = __shfl_xor_sync(FULL, i1, 4);
        }

        if (lane == 0) {
            float* o = out + (b << 10) + p7;
            #pragma unroll
            for (int q = 0; q < 8; q++) o[q << 7] = a4[q];
        }
    }
}

extern "C" void kernel_launch(void* const* d_in, const int* in_sizes, int n_in,
                              void* d_out, int out_size) {
    const float* M = (const float*)d_in[0];
    float* out = (float*)d_out;
    (void)in_sizes; (void)n_in; (void)out_size;

    cnndst_fused<<<dim3(64, 64), 256>>>(M, out);
}

// round 9
// speedup vs baseline: 1.3471x; 1.3471x over previous
#include <cuda_runtime.h>
#include <cuda_bf16.h>

// Quadtree contraction: out[b][i] applies, at level k=1..10 (finest first),
//   choice c_k = bit_{k-1}(i):  c=0 -> x[2r,2c]+x[2r,2c+1]+x[2r+1,2c]
//                               c=1 -> x[2r+1,2c+1]
// Stage 1: block = one 128x128 tile. Levels 1..3 in registers (thread owns an
//          8x8 fine block), levels 4..7 in shared. Emits g_scratch[b][p7][tile]
//          (8x8 grid per (b, 7-bit prefix)). 2 MB scratch.
//          __launch_bounds__(256,3) -> <=85 regs so all 16 LDG.128 front-batch.
// Stage 2: one warp per 4 consecutive (b,p7): 8 front-batched loads, 4
//          independent shuffle trees (levels 8..10), lane0 stores 8 float4.

static __device__ float g_scratch[64 * 128 * 64]; // 2 MB: [((b<<7)|p7)<<6 | tile]

__global__ __launch_bounds__(256, 3) void cnndst_stage1(const float* __restrict__ M) {
    __shared__ float bufA[2048]; // level3 [p3(8)][t(256)], later level5 (512)
    __shared__ float bufB[1024]; // level4 [p4(16)][cell(64)], later level6 (256)

    const int tid  = threadIdx.x;
    const int b    = blockIdx.y;
    const int tile = blockIdx.x;       // 0..63
    const int tr   = tile >> 3;
    const int tc   = tile & 7;

    // Thread's 8x8 fine block at rows (tid>>4)*8, cols (tid&15)*8 of the tile.
    const float* src = M + ((size_t)b << 20)
                         + ((size_t)((tr << 7) + ((tid >> 4) << 3))) * 1024
                         + (size_t)((tc << 7) + ((tid & 15) << 3));

    // Front-batched streaming loads (read-once input; evict-first).
    float4 L[16];
    #pragma unroll
    for (int rr = 0; rr < 8; rr++) {
        L[2 * rr]     = __ldcs((const float4*)(src + (size_t)rr * 1024));
        L[2 * rr + 1] = __ldcs((const float4*)(src + (size_t)rr * 1024 + 4));
    }

    // Level 1 in registers: 4x4 S grid + 4x4 D grid.
    float s1[4][4], d1[4][4];
    #pragma unroll
    for (int rr = 0; rr < 4; rr++) {
        const float4 a0 = L[4 * rr],     a1 = L[4 * rr + 1];
        const float4 b0 = L[4 * rr + 2], b1 = L[4 * rr + 3];
        s1[rr][0] = (a0.x + a0.y) + b0.x;  d1[rr][0] = b0.y;
        s1[rr][1] = (a0.z + a0.w) + b0.z;  d1[rr][1] = b0.w;
        s1[rr][2] = (a1.x + a1.y) + b1.x;  d1[rr][2] = b1.y;
        s1[rr][3] = (a1.z + a1.w) + b1.z;  d1[rr][3] = b1.w;
    }
    // Level 2: p2 = c1 + 2*c2 -> grids 0:S(s1) 1:S(d1) 2:D(s1) 3:D(d1).
    float g2[4][2][2];
    #pragma unroll
    for (int r = 0; r < 2; r++)
        #pragma unroll
        for (int c = 0; c < 2; c++) {
            g2[0][r][c] = (s1[2*r][2*c] + s1[2*r][2*c+1]) + s1[2*r+1][2*c];
            g2[2][r][c] = s1[2*r+1][2*c+1];
            g2[1][r][c] = (d1[2*r][2*c] + d1[2*r][2*c+1]) + d1[2*r+1][2*c];
            g2[3][r][c] = d1[2*r+1][2*c+1];
        }
    // Level 3: thread sits at (tid>>4, tid&15) of each 16x16 level-3 grid.
    #pragma unroll
    for (int p = 0; p < 4; p++) {
        bufA[(p << 8) + tid]       = (g2[p][0][0] + g2[p][0][1]) + g2[p][1][0];
        bufA[((p + 4) << 8) + tid] = g2[p][1][1];
    }
    __syncthreads();

    // Level 4: 8 grids 16x16 -> 16 grids 8x8. 512 units, 2/thread.
    #pragma unroll
    for (int k = 0; k < 2; k++) {
        const int idx  = tid + (k << 8);
        const int p    = idx >> 6, cell = idx & 63;
        const int r    = cell >> 3, c = cell & 7;
        const float* in = bufA + (p << 8) + (r << 5) + (c << 1);
        bufB[(p << 6) + cell]       = (in[0] + in[1]) + in[16];
        bufB[((p + 8) << 6) + cell] = in[17];
    }
    __syncthreads();

    // Level 5: 16 grids 8x8 -> 32 grids 4x4. 256 units, 1/thread.
    {
        const int p = tid >> 4, cell = tid & 15;
        const int r = cell >> 2, c = cell & 3;
        const float* in = bufB + (p << 6) + (r << 4) + (c << 1);
        bufA[(p << 4) + cell]        = (in[0] + in[1]) + in[8];
        bufA[((p + 16) << 4) + cell] = in[9];
    }
    __syncthreads();

    // Level 6: 32 grids 4x4 -> 64 grids 2x2. 128 units.
    if (tid < 128) {
        const int p = tid >> 2, cell = tid & 3;
        const int r = cell >> 1, c = cell & 1;
        const float* in = bufA + (p << 4) + (r << 3) + (c << 1);
        bufB[(p << 2) + cell]        = (in[0] + in[1]) + in[4];
        bufB[((p + 32) << 2) + cell] = in[5];
    }
    __syncthreads();

    // Level 7: 64 grids 2x2 -> 128 scalars -> g_scratch.
    if (tid < 64) {
        const float* in = bufB + (tid << 2);
        const int base = (b << 7);
        g_scratch[((size_t)(base + tid) << 6) + tile]      = (in[0] + in[1]) + in[2];
        g_scratch[((size_t)(base + tid + 64) << 6) + tile] = in[3];
    }
}

// Stage 2: warp handles 4 consecutive p7. Lane layout on each 8x8 grid:
// k = reg*32 + lane, (r,c) = (k>>3, k&7).
__global__ __launch_bounds__(256) void cnndst_stage2(float* __restrict__ out) {
    const int tid  = threadIdx.x;
    const int lane = tid & 31;
    const int W    = (blockIdx.x << 3) + (tid >> 5);  // global warp id, 0..2047
    const int b    = W >> 5;                          // 32 warp-chunks per batch
    const int p7b  = (W & 31) << 2;                   // p7 base (multiple of 4)

    const float* g0 = g_scratch + (((size_t)((b << 7) + p7b)) << 6);

    // Front-batch 8 independent loads (4 grids x 2 rows-of-32).
    float v0[4], v1[4];
    #pragma unroll
    for (int it = 0; it < 4; it++) {
        v0[it] = g0[(it << 6) + lane];
        v1[it] = g0[(it << 6) + 32 + lane];
    }

    const unsigned FULL = 0xffffffffu;
    float res[4][8];

    #pragma unroll
    for (int it = 0; it < 4; it++) {
        // Level 8: 8x8 -> 2 grids 4x4 (valid at even r, even c lanes).
        float a1[2][2];
        {
            const float x01a = __shfl_xor_sync(FULL, v0[it], 1);
            const float x10a = __shfl_xor_sync(FULL, v0[it], 8);
            const float x11a = __shfl_xor_sync(FULL, v0[it], 9);
            a1[0][0] = (v0[it] + x01a) + x10a;
            a1[1][0] = x11a;
            const float x01b = __shfl_xor_sync(FULL, v1[it], 1);
            const float x10b = __shfl_xor_sync(FULL, v1[it], 8);
            const float x11b = __shfl_xor_sync(FULL, v1[it], 9);
            a1[0][1] = (v1[it] + x01b) + x10b;
            a1[1][1] = x11b;
        }
        // Level 9: sparse spacing 2 -> xor 2 horiz, 16 vert.
        float a2[4][2];
        #pragma unroll
        for (int p = 0; p < 2; p++)
            #pragma unroll
            for (int i = 0; i < 2; i++) {
                const float x00 = a1[p][i];
                const float x01 = __shfl_xor_sync(FULL, x00, 2);
                const float x10 = __shfl_xor_sync(FULL, x00, 16);
                const float x11 = __shfl_xor_sync(FULL, x00, 18);
                a2[p][i]     = (x00 + x01) + x10;
                a2[p + 2][i] = x11;
            }
        // Level 10: sparse spacing 4 -> xor 4 horiz; vertical = cross-reg.
        #pragma unroll
        for (int p = 0; p < 4; p++) {
            const float i0 = a2[p][0];
            const float i1 = a2[p][1];
            res[it][p]     = (i0 + __shfl_xor_sync(FULL, i0, 4)) + i1;
            res[it][p + 4] = __shfl_xor_sync(FULL, i1, 4);
        }
    }

    // Lane 0 stores: for each q, 4 consecutive p7 -> one float4.
    if (lane == 0) {
        float* o = out + (b << 10) + p7b;
        #pragma unroll
        for (int q = 0; q < 8; q++) {
            float4 w;
            w.x = res[0][q]; w.y = res[1][q]; w.z = res[2][q]; w.w = res[3][q];
            *(float4*)(o + (q << 7)) = w;
        }
    }
}

extern "C" void kernel_launch(void* const* d_in, const int* in_sizes, int n_in,
                              void* d_out, int out_size) {
    const float* M = (const float*)d_in[0];
    float* out = (float*)d_out;
    (void)in_sizes; (void)n_in; (void)out_size;

    cnndst_stage1<<<dim3(64, 64), 256>>>(M);
    cnndst_stage2<<<256, 256>>>(out);
}

// round 10
// speedup vs baseline: 1.4602x; 1.0839x over previous
#include <cuda_runtime.h>
#include <cuda_bf16.h>

// Quadtree contraction: out[b][i] applies, at level k=1..10 (finest first),
//   choice c_k = bit_{k-1}(i):  c=0 -> x[2r,2c]+x[2r,2c+1]+x[2r+1,2c]
//                               c=1 -> x[2r+1,2c+1]
//
// Single-pass formulation: block = one 128x128 tile t=(tr,tc) of batch b.
// Levels 1..3 in registers, 4..7 in shared -> 128 scalars s[p7].
// Levels 8..10 are LINEAR over tile scalars and their supports PARTITION the
// 8x8 tile grid: tile t contributes (weight 1) to exactly one output suffix
//   q(t) = tr & tc   (bitwise, 3-bit),
// so  out[b][q<<7 | p7] = sum over tiles with tr&tc==q of s[b][p7][t].
// Each block therefore atomicAdds its 128 scalars directly into out.
// No scratch, no second reduction kernel. out is zeroed by a tiny kernel first.

__global__ void cnndst_zero(float* __restrict__ out) {
    const int gid = blockIdx.x * 256 + threadIdx.x;   // 16384 threads
    *(float4*)(out + (gid << 2)) = make_float4(0.f, 0.f, 0.f, 0.f);
}

__global__ __launch_bounds__(256, 3) void cnndst_main(const float* __restrict__ M,
                                                      float* __restrict__ out) {
    __shared__ float bufA[2048]; // level3 [p3(8)][t(256)], later level5 (512)
    __shared__ float bufB[1024]; // level4 [p4(16)][cell(64)], later level6 (256)

    const int tid  = threadIdx.x;
    const int b    = blockIdx.y;
    const int tile = blockIdx.x;       // 0..63
    const int tr   = tile >> 3;
    const int tc   = tile & 7;

    // Thread's 8x8 fine block at rows (tid>>4)*8, cols (tid&15)*8 of the tile.
    const float* src = M + ((size_t)b << 20)
                         + ((size_t)((tr << 7) + ((tid >> 4) << 3))) * 1024
                         + (size_t)((tc << 7) + ((tid & 15) << 3));

    // Front-batched streaming loads (read-once input; evict-first).
    float4 L[16];
    #pragma unroll
    for (int rr = 0; rr < 8; rr++) {
        L[2 * rr]     = __ldcs((const float4*)(src + (size_t)rr * 1024));
        L[2 * rr + 1] = __ldcs((const float4*)(src + (size_t)rr * 1024 + 4));
    }

    // Level 1 in registers: 4x4 S grid + 4x4 D grid.
    float s1[4][4], d1[4][4];
    #pragma unroll
    for (int rr = 0; rr < 4; rr++) {
        const float4 a0 = L[4 * rr],     a1 = L[4 * rr + 1];
        const float4 b0 = L[4 * rr + 2], b1 = L[4 * rr + 3];
        s1[rr][0] = (a0.x + a0.y) + b0.x;  d1[rr][0] = b0.y;
        s1[rr][1] = (a0.z + a0.w) + b0.z;  d1[rr][1] = b0.w;
        s1[rr][2] = (a1.x + a1.y) + b1.x;  d1[rr][2] = b1.y;
        s1[rr][3] = (a1.z + a1.w) + b1.z;  d1[rr][3] = b1.w;
    }
    // Level 2: p2 = c1 + 2*c2 -> grids 0:S(s1) 1:S(d1) 2:D(s1) 3:D(d1).
    float g2[4][2][2];
    #pragma unroll
    for (int r = 0; r < 2; r++)
        #pragma unroll
        for (int c = 0; c < 2; c++) {
            g2[0][r][c] = (s1[2*r][2*c] + s1[2*r][2*c+1]) + s1[2*r+1][2*c];
            g2[2][r][c] = s1[2*r+1][2*c+1];
            g2[1][r][c] = (d1[2*r][2*c] + d1[2*r][2*c+1]) + d1[2*r+1][2*c];
            g2[3][r][c] = d1[2*r+1][2*c+1];
        }
    // Level 3: thread sits at (tid>>4, tid&15) of each 16x16 level-3 grid.
    #pragma unroll
    for (int p = 0; p < 4; p++) {
        bufA[(p << 8) + tid]       = (g2[p][0][0] + g2[p][0][1]) + g2[p][1][0];
        bufA[((p + 4) << 8) + tid] = g2[p][1][1];
    }
    __syncthreads();

    // Level 4: 8 grids 16x16 -> 16 grids 8x8. 512 units, 2/thread.
    #pragma unroll
    for (int k = 0; k < 2; k++) {
        const int idx  = tid + (k << 8);
        const int p    = idx >> 6, cell = idx & 63;
        const int r    = cell >> 3, c = cell & 7;
        const float* in = bufA + (p << 8) + (r << 5) + (c << 1);
        bufB[(p << 6) + cell]       = (in[0] + in[1]) + in[16];
        bufB[((p + 8) << 6) + cell] = in[17];
    }
    __syncthreads();

    // Level 5: 16 grids 8x8 -> 32 grids 4x4. 256 units, 1/thread.
    {
        const int p = tid >> 4, cell = tid & 15;
        const int r = cell >> 2, c = cell & 3;
        const float* in = bufB + (p << 6) + (r << 4) + (c << 1);
        bufA[(p << 4) + cell]        = (in[0] + in[1]) + in[8];
        bufA[((p + 16) << 4) + cell] = in[9];
    }
    __syncthreads();

    // Level 6: 32 grids 4x4 -> 64 grids 2x2. 128 units.
    if (tid < 128) {
        const int p = tid >> 2, cell = tid & 3;
        const int r = cell >> 1, c = cell & 1;
        const float* in = bufA + (p << 4) + (r << 3) + (c << 1);
        bufB[(p << 2) + cell]        = (in[0] + in[1]) + in[4];
        bufB[((p + 32) << 2) + cell] = in[5];
    }
    __syncthreads();

    // Level 7 + direct accumulation of levels 8..10:
    // tile contributes its scalars to output suffix q = tr & tc only.
    if (tid < 64) {
        const float* in = bufB + (tid << 2);
        const float vS = (in[0] + in[1]) + in[2];   // p7 = tid      (c7 = 0)
        const float vD = in[3];                     // p7 = tid + 64 (c7 = 1)
        const int q = tr & tc;                      // 3-bit suffix (c8,c9,c10)
        float* o = out + (b << 10) + (q << 7);
        atomicAdd(o + tid,      vS);
        atomicAdd(o + tid + 64, vD);
    }
}

extern "C" void kernel_launch(void* const* d_in, const int* in_sizes, int n_in,
                              void* d_out, int out_size) {
    const float* M = (const float*)d_in[0];
    float* out = (float*)d_out;
    (void)in_sizes; (void)n_in; (void)out_size;

    cnndst_zero<<<64, 256>>>(out);
    cnndst_main<<<dim3(64, 64), 256>>>(M, out);
}